// round 1
// baseline (speedup 1.0000x reference)
#include <cuda_runtime.h>
#include <cuda_bf16.h>
#include <stdint.h>

// Canny non-max suppression, collapsed form.
// Directional filter k == center - neighbor_k; idx_neg = idx_pos+4 is the
// opposite direction. Per pixel:
//   pos = m + bias[i]       - m[y+dy, x+dx]
//   neg = m + bias[(i+4)&7] - m[y-dy, x-dx]
//   out = (min(pos,neg) > 0) ? m : 0
// SAME zero padding -> out-of-range neighbor contributes 0.

#define IMG_H 4096
#define IMG_W 4096

// dx per idx: {1,1,0,-1,-1,-1,0,1} -> (dx+1) 2-bit packed
// dy per idx: {0,1,1,1,0,-1,-1,-1} -> (dy+1) 2-bit packed
#define DX_PACK 36890u  // 2,2,1,0,0,0,1,2
#define DY_PACK 425u    // 1,2,2,2,1,0,0,0

__global__ __launch_bounds__(256) void nms_kernel(
    const float* __restrict__ mag,
    const float* __restrict__ ori,
    const float* __restrict__ bias,
    float* __restrict__ out)
{
    const int x4 = blockIdx.x * blockDim.x + threadIdx.x;   // unit of 4 pixels
    const int y  = blockIdx.y * blockDim.y + threadIdx.y;
    const int x  = x4 << 2;
    if (x >= IMG_W || y >= IMG_H) return;

    const size_t base = (size_t)y * IMG_W + x;
    const float4 m4 = *reinterpret_cast<const float4*>(mag + base);
    const float4 o4 = *reinterpret_cast<const float4*>(ori + base);

    float mm[4] = {m4.x, m4.y, m4.z, m4.w};
    float oo[4] = {o4.x, o4.y, o4.z, o4.w};
    float rr[4];

#pragma unroll
    for (int i = 0; i < 4; i++) {
        const int idx = ((int)(oo[i] * (1.0f / 45.0f))) & 7;
        const int sh  = idx << 1;
        const int dx  = (int)((DX_PACK >> sh) & 3u) - 1;
        const int dy  = (int)((DY_PACK >> sh) & 3u) - 1;
        const int xi  = x + i;

        // forward neighbor
        const int ny = y + dy, nx = xi + dx;
        float np = 0.0f;
        if ((unsigned)ny < IMG_H && (unsigned)nx < IMG_W)
            np = __ldg(mag + (size_t)ny * IMG_W + nx);

        // backward neighbor
        const int my = y - dy, mx = xi - dx;
        float nn = 0.0f;
        if ((unsigned)my < IMG_H && (unsigned)mx < IMG_W)
            nn = __ldg(mag + (size_t)my * IMG_W + mx);

        const float bpos = __ldg(bias + idx);
        const float bneg = __ldg(bias + ((idx + 4) & 7));

        const float pos = mm[i] + bpos - np;
        const float neg = mm[i] + bneg - nn;
        rr[i] = (fminf(pos, neg) > 0.0f) ? mm[i] : 0.0f;
    }

    *reinterpret_cast<float4*>(out + base) = make_float4(rr[0], rr[1], rr[2], rr[3]);
}

extern "C" void kernel_launch(void* const* d_in, const int* in_sizes, int n_in,
                              void* d_out, int out_size)
{
    const float* mag  = (const float*)d_in[0];   // grad_magnitude [1,1,4096,4096]
    const float* ori  = (const float*)d_in[1];   // grad_orientation [1,1,4096,4096]
    // d_in[2] = weight [8,1,3,3] -- structure hardcoded (fixed directional filters)
    const float* bias = (const float*)d_in[3];   // bias [8]
    float* out = (float*)d_out;

    dim3 block(32, 8);                            // covers 128 x 8 pixel tile
    dim3 grid(IMG_W / (32 * 4), IMG_H / 8);       // (32, 512)
    nms_kernel<<<grid, block>>>(mag, ori, bias, out);
}